// round 16
// baseline (speedup 1.0000x reference)
#include <cuda_runtime.h>
#include <cuda_bf16.h>
#include <cstdint>

#define NN 100000
#define EE 600000
#define GG 1000
#define GT128 782    // ceil(NN/128)
#define NB 391       // ceil(NN/256)
#define NSM 148
#define CHUNK_T 391          // tiles in chunk0
#define CHUNK_N (CHUNK_T*128) // 50048 nodes in chunk0

// ---------------- static device scratch --------------------------------------
__device__ float d_dinv[NN];
__device__ uint32_t d_g[(size_t)NN * 64];    // ping: p packed bf16x2 (128 bf16/row)
__device__ uint32_t d_h[(size_t)NN * 64];    // pong
__device__ uint32_t d_ahi[(size_t)NN * 64];  // A packed bf16
__device__ float d_pool[GG * 128];
__device__ float d_pcnt[GG];
__device__ int   d_cnti[NN];
__device__ int   d_off[NN + 1];
__device__ int   d_cur[NN];
__device__ int   d_csr[EE];
__device__ int   d_bsum[NB + 1];
__device__ __nv_bfloat16 d_whi[3 * 128 * 128];   // W^T bf16 high, [layer][n][k]
__device__ __nv_bfloat16 d_wlo[3 * 128 * 128];   // W^T bf16 low

// ---------------- helpers ------------------------------------------------------
__device__ __forceinline__ uint32_t smem_u32(const void* p) {
    uint32_t a;
    asm("{ .reg .u64 t; cvta.to.shared.u64 t, %1; cvt.u32.u64 %0, t; }" : "=r"(a) : "l"(p));
    return a;
}
#define LDM_X4(r, addr) \
    asm volatile("ldmatrix.sync.aligned.m8n8.x4.shared.b16 {%0,%1,%2,%3}, [%4];" \
        : "=r"((r)[0]), "=r"((r)[1]), "=r"((r)[2]), "=r"((r)[3]) : "r"(addr))

__device__ __forceinline__ void mma_bf16(float* c, const uint32_t* a, const uint32_t* b) {
    asm volatile("mma.sync.aligned.m16n8k16.row.col.f32.bf16.bf16.f32 "
        "{%0,%1,%2,%3}, {%4,%5,%6,%7}, {%8,%9}, {%0,%1,%2,%3};"
        : "+f"(c[0]), "+f"(c[1]), "+f"(c[2]), "+f"(c[3])
        : "r"(a[0]), "r"(a[1]), "r"(a[2]), "r"(a[3]), "r"(b[0]), "r"(b[1]));
}

__device__ __forceinline__ uint32_t pkbf(float a, float b) {
    __nv_bfloat162 t = __floats2bfloat162_rn(a, b);
    return *(uint32_t*)&t;
}
__device__ __forceinline__ void b2f8(uint4 u, float* f) {
    float2 f0 = __bfloat1622float2(*(__nv_bfloat162*)&u.x);
    float2 f1 = __bfloat1622float2(*(__nv_bfloat162*)&u.y);
    float2 f2 = __bfloat1622float2(*(__nv_bfloat162*)&u.z);
    float2 f3 = __bfloat1622float2(*(__nv_bfloat162*)&u.w);
    f[0] = f0.x; f[1] = f0.y; f[2] = f1.x; f[3] = f1.y;
    f[4] = f2.x; f[5] = f2.y; f[6] = f3.x; f[7] = f3.y;
}

// CSR gather, half-warp per node: lane l (0..15) owns cols 8l..8l+7 (one uint4).
__device__ __forceinline__ void gather_row_bf8(const uint4* __restrict__ P,
                                               int m, int l, float* out8) {
    float a[8], b[8];
    b2f8(__ldg(&P[(size_t)m * 16 + l]), a);
#pragma unroll
    for (int i = 0; i < 8; i++) b[i] = 0.f;
    int beg = __ldg(&d_off[m]), end = __ldg(&d_off[m + 1]);
    int e = beg;
    for (; e + 1 < end; e += 2) {
        int s0 = __ldg(&d_csr[e]);
        int s1 = __ldg(&d_csr[e + 1]);
        uint4 u0 = __ldg(&P[(size_t)s0 * 16 + l]);
        uint4 u1 = __ldg(&P[(size_t)s1 * 16 + l]);
        float x0[8], x1[8];
        b2f8(u0, x0);
        b2f8(u1, x1);
#pragma unroll
        for (int i = 0; i < 8; i++) { a[i] += x0[i]; b[i] += x1[i]; }
    }
    if (e < end) {
        int s0 = __ldg(&d_csr[e]);
        float x0[8];
        b2f8(__ldg(&P[(size_t)s0 * 16 + l]), x0);
#pragma unroll
        for (int i = 0; i < 8; i++) a[i] += x0[i];
    }
#pragma unroll
    for (int i = 0; i < 8; i++) out8[i] = a[i] + b[i];
}

// ---------------- init / degree / CSR ------------------------------------------
__global__ void k_init() {
    int i = blockIdx.x * 256 + threadIdx.x;
    if (i < NN) d_cnti[i] = 0;
    if (i < GG * 128) d_pool[i] = 0.f;
    if (i < GG) d_pcnt[i] = 0.f;
}
__global__ void k_count(const int* __restrict__ dst) {
    int e = blockIdx.x * 256 + threadIdx.x;
    if (e < EE) atomicAdd(&d_cnti[dst[e]], 1);
}
__global__ void k_scan1() {
    __shared__ int s[256];
    int b = blockIdx.x, t = threadIdx.x;
    int i = b * 256 + t;
    int v = (i < NN) ? d_cnti[i] : 0;
    if (i < NN) d_dinv[i] = rsqrtf((float)(v + 1));
    s[t] = v;
    __syncthreads();
#pragma unroll
    for (int off = 1; off < 256; off <<= 1) {
        int x = (t >= off) ? s[t - off] : 0;
        __syncthreads();
        s[t] += x;
        __syncthreads();
    }
    if (i < NN) d_off[i] = s[t] - v;
    if (t == 255) d_bsum[b] = s[255];
}
__global__ void k_scan3() {
    __shared__ int sh[256];
    int b = blockIdx.x, t = threadIdx.x;
    int part = 0;
    for (int i = t; i < b; i += 256) part += d_bsum[i];
    sh[t] = part;
    __syncthreads();
#pragma unroll
    for (int off = 128; off > 0; off >>= 1) {
        if (t < off) sh[t] += sh[t + off];
        __syncthreads();
    }
    int base = sh[0];
    int i = b * 256 + t;
    if (i < NN) {
        int o = d_off[i] + base;
        d_off[i] = o;
        d_cur[i] = o;
    }
    if (i == 0) d_off[NN] = EE;
}
__global__ void k_fill(const int* __restrict__ src, const int* __restrict__ dst) {
    int e = blockIdx.x * 256 + threadIdx.x;
    if (e < EE) {
        int pos = atomicAdd(&d_cur[dst[e]], 1);
        d_csr[pos] = src[e];
    }
}

// ---------------- all W -> bf16 hi/lo, transposed [n][k] -----------------------
__global__ void k_wconv_all(const float* __restrict__ W1, const float* __restrict__ W2,
                            const float* __restrict__ W3) {
    int idx = blockIdx.x * 256 + threadIdx.x;
    int layer = idx >> 14;
    int r = idx & 16383;
    const float* W = (layer == 0) ? W1 : (layer == 1) ? W2 : W3;
    int n = r & 127, k = r >> 7;
    float wv = __ldg(&W[k * 128 + n]);
    __nv_bfloat16 hb = __float2bfloat16_rn(wv);
    __nv_bfloat16 lb = __float2bfloat16_rn(wv - __bfloat162float(hb));
    d_whi[layer * 16384 + n * 128 + k] = hb;
    d_wlo[layer * 16384 + n * 128 + k] = lb;
}

// ---------------- layer 0: p0 = bf16(dinv * (x @ W0)), K=4 --------------------
__global__ void k_gemm0(const float* __restrict__ x, const float* __restrict__ W0) {
    int t = threadIdx.x;
    int j = t & 31;
    float w[16];
#pragma unroll
    for (int k = 0; k < 4; k++)
#pragma unroll
        for (int c = 0; c < 4; c++)
            w[k * 4 + c] = __ldg(&W0[k * 128 + j * 4 + c]);
    int gw = blockIdx.x * 8 + (t >> 5);
    for (int n = gw; n < NN; n += gridDim.x * 8) {
        float4 xv = __ldg((const float4*)x + n);
        float di = d_dinv[n];
        float4 r;
        r.x = di * (xv.x * w[0] + xv.y * w[4] + xv.z * w[8]  + xv.w * w[12]);
        r.y = di * (xv.x * w[1] + xv.y * w[5] + xv.z * w[9]  + xv.w * w[13]);
        r.z = di * (xv.x * w[2] + xv.y * w[6] + xv.z * w[10] + xv.w * w[14]);
        r.w = di * (xv.x * w[3] + xv.y * w[7] + xv.z * w[11] + xv.w * w[15]);
        ((uint2*)d_g)[(size_t)n * 32 + j] = make_uint2(pkbf(r.x, r.y), pkbf(r.z, r.w));
    }
}

// ---- gather + transform: A[v] = bf16(relu(dinv*s + b)), half-warp/node --------
__global__ void k_gatherA(const uint32_t* __restrict__ in, const float* __restrict__ bias,
                          int n0) {
    int v = n0 + blockIdx.x * 16 + (threadIdx.x >> 4);   // exact grids
    int l = threadIdx.x & 15;
    float s[8];
    gather_row_bf8((const uint4*)in, v, l, s);
    float di = __ldg(&d_dinv[v]);
    float4 b0 = __ldg((const float4*)bias + 2 * l);
    float4 b1 = __ldg((const float4*)bias + 2 * l + 1);
    float a0 = fmaxf(fmaf(di, s[0], b0.x), 0.f);
    float a1 = fmaxf(fmaf(di, s[1], b0.y), 0.f);
    float a2 = fmaxf(fmaf(di, s[2], b0.z), 0.f);
    float a3 = fmaxf(fmaf(di, s[3], b0.w), 0.f);
    float a4 = fmaxf(fmaf(di, s[4], b1.x), 0.f);
    float a5 = fmaxf(fmaf(di, s[5], b1.y), 0.f);
    float a6 = fmaxf(fmaf(di, s[6], b1.z), 0.f);
    float a7 = fmaxf(fmaf(di, s[7], b1.w), 0.f);
    uint4 o;
    o.x = pkbf(a0, a1); o.y = pkbf(a2, a3);
    o.z = pkbf(a4, a5); o.w = pkbf(a6, a7);
    ((uint4*)d_ahi)[(size_t)v * 16 + l] = o;
}

// ---------------- persistent HMMA GEMM over tile range [tb, te) ---------------
#define PITCH 136
#define A_BUF0 0
#define A_BUF1 34816
#define B_HI 69632
#define B_LO 104448
#define SMEM_MMA 139264

__global__ void __launch_bounds__(512) k_gemm_mma(int layer, uint32_t* __restrict__ out,
                                                  int tb, int te) {
    extern __shared__ char smb[];
    uint32_t sbase = smem_u32(smb);
    int t = threadIdx.x, w = t >> 5, l = t & 31;

    const uint4* AH = (const uint4*)d_ahi;
    int tile0 = tb + blockIdx.x;

    // ---- prologue: async-load A(tile0) into buf0 ----
    if (tile0 < te) {
        int m128 = tile0 * 128;
#pragma unroll
        for (int i = t; i < 2048; i += 512) {
            int r = i >> 4, j = i & 15;
            int m = m128 + r;
            int mc = (m < NN) ? m : (NN - 1);
            int pb = (m < NN) ? 16 : 0;
            uint32_t dst = sbase + A_BUF0 + (uint32_t)((r * PITCH + j * 8) * 2);
            asm volatile("cp.async.cg.shared.global [%0], [%1], 16, %2;"
                         :: "r"(dst), "l"(&AH[(size_t)mc * 16 + j]), "r"(pb));
        }
        asm volatile("cp.async.commit_group;" ::: "memory");
    }

    // ---- W hi/lo into smem (once) ----
    const uint4* WH = (const uint4*)(d_whi + layer * 16384);
    const uint4* WL = (const uint4*)(d_wlo + layer * 16384);
#pragma unroll
    for (int i = t; i < 2048; i += 512) {
        int n = i >> 4, k8 = (i & 15) * 8;
        int off = (n * PITCH + k8) * 2;
        *(uint4*)(smb + B_HI + off) = __ldg(&WH[i]);
        *(uint4*)(smb + B_LO + off) = __ldg(&WL[i]);
    }
    asm volatile("cp.async.wait_group 0;" ::: "memory");
    __syncthreads();

    // ---- per-warp constant fragment addressing ----
    int rs = (w >> 1) * 16;
    int cb = (w & 1) * 64;
    int arow = rs + (l & 7) + ((l >> 3) & 1) * 8;
    int acol8 = (l >> 4) * 8;
    uint32_t a_frag = sbase + (uint32_t)((arow * PITCH + acol8) * 2);
    int brow = (l & 7) + (l >> 4) * 8;
    int bk8  = ((l >> 3) & 1) * 8;

    int par = 0;
    for (int tile = tile0; tile < te; tile += gridDim.x, par ^= 1) {
        // ---- prefetch next A tile into the other buffer ----
        int next = tile + gridDim.x;
        if (next < te) {
            int m128 = next * 128;
            uint32_t boff = (par == 0) ? A_BUF1 : A_BUF0;
#pragma unroll
            for (int i = t; i < 2048; i += 512) {
                int r = i >> 4, j = i & 15;
                int m = m128 + r;
                int mc = (m < NN) ? m : (NN - 1);
                int pb = (m < NN) ? 16 : 0;
                uint32_t dst = sbase + boff + (uint32_t)((r * PITCH + j * 8) * 2);
                asm volatile("cp.async.cg.shared.global [%0], [%1], 16, %2;"
                             :: "r"(dst), "l"(&AH[(size_t)mc * 16 + j]), "r"(pb));
            }
            asm volatile("cp.async.commit_group;" ::: "memory");
        }

        // ---- MMA on current buffer ----
        uint32_t a_base = a_frag + (par ? A_BUF1 : A_BUF0);
        float acc[32];
#pragma unroll
        for (int i = 0; i < 32; i++) acc[i] = 0.f;

#pragma unroll
        for (int kb = 0; kb < 8; kb++) {
            int k0 = kb * 16;
            uint32_t ah[4];
            LDM_X4(ah, a_base + k0 * 2);
#pragma unroll
            for (int np = 0; np < 4; np++) {
                int nb = cb + np * 16;
                uint32_t boff2 = (uint32_t)(((nb + brow) * PITCH + k0 + bk8) * 2);
                uint32_t bh[4], bl[4];
                LDM_X4(bh, sbase + B_HI + boff2);
                LDM_X4(bl, sbase + B_LO + boff2);
                float* c = acc + np * 8;
                mma_bf16(c,     ah, bh);
                mma_bf16(c,     ah, bl);
                mma_bf16(c + 4, ah, bh + 2);
                mma_bf16(c + 4, ah, bl + 2);
            }
        }

        // ---- epilogue: scale rows by dinv, store packed bf16 p ----
        int r0 = tile * 128 + rs + (l >> 2);
        int r1 = r0 + 8;
        float d0 = (r0 < NN) ? d_dinv[r0] : 0.f;
        float d1 = (r1 < NN) ? d_dinv[r1] : 0.f;
#pragma unroll
        for (int nt = 0; nt < 8; nt++) {
            int col = cb + nt * 8 + (l & 3) * 2;
            float* a = acc + nt * 4;
            if (r0 < NN) out[(size_t)r0 * 64 + (col >> 1)] = pkbf(a[0] * d0, a[1] * d0);
            if (r1 < NN) out[(size_t)r1 * 64 + (col >> 1)] = pkbf(a[2] * d1, a[3] * d1);
        }

        if (next < te)
            asm volatile("cp.async.wait_group 0;" ::: "memory");
        __syncthreads();
    }
}

// ---------------- fused gather + pooling (half-warp per node) ------------------
__global__ void k_gpool(const uint32_t* __restrict__ in, const int* __restrict__ batch,
                        const float* __restrict__ b3) {
    int v = blockIdx.x * 16 + (threadIdx.x >> 4);   // grid NN/16 exact
    int l = threadIdx.x & 15;
    float s[8];
    gather_row_bf8((const uint4*)in, v, l, s);
    float di = __ldg(&d_dinv[v]);
    float4 bb0 = __ldg((const float4*)b3 + 2 * l);
    float4 bb1 = __ldg((const float4*)b3 + 2 * l + 1);
    float o0 = fmaxf(fmaf(di, s[0], bb0.x), 0.f);
    float o1 = fmaxf(fmaf(di, s[1], bb0.y), 0.f);
    float o2 = fmaxf(fmaf(di, s[2], bb0.z), 0.f);
    float o3 = fmaxf(fmaf(di, s[3], bb0.w), 0.f);
    float o4 = fmaxf(fmaf(di, s[4], bb1.x), 0.f);
    float o5 = fmaxf(fmaf(di, s[5], bb1.y), 0.f);
    float o6 = fmaxf(fmaf(di, s[6], bb1.z), 0.f);
    float o7 = fmaxf(fmaf(di, s[7], bb1.w), 0.f);
    int g = __ldg(&batch[v]);
    float* p = d_pool + g * 128 + l * 8;
    asm volatile("red.global.add.v4.f32 [%0], {%1,%2,%3,%4};"
                 :: "l"(p), "f"(o0), "f"(o1), "f"(o2), "f"(o3) : "memory");
    asm volatile("red.global.add.v4.f32 [%0], {%1,%2,%3,%4};"
                 :: "l"(p + 4), "f"(o4), "f"(o5), "f"(o6), "f"(o7) : "memory");
    if (l == 0) atomicAdd(&d_pcnt[g], 1.0f);
}

// ---------------- final MLP ----------------------------------------------------
__global__ void k_mlp(const float* __restrict__ xs, const float* __restrict__ Wl1,
                      const float* __restrict__ bl1, const float* __restrict__ Wl2,
                      const float* __restrict__ bl2, float* __restrict__ out) {
    __shared__ float feat[132];
    __shared__ float part[64];
    int g = blockIdx.x, t = threadIdx.x;
    float inv = 1.0f / fmaxf(d_pcnt[g], 1.0f);
    for (int i = t; i < 132; i += 64)
        feat[i] = (i < 128) ? d_pool[g * 128 + i] * inv : xs[g * 4 + (i - 128)];
    __syncthreads();
    float h = bl1[t];
#pragma unroll 4
    for (int i = 0; i < 132; i++) h = fmaf(feat[i], Wl1[i * 64 + t], h);
    h = fmaxf(h, 0.f);
    part[t] = h * Wl2[t];
    __syncthreads();
    if (t == 0) {
        float s = bl2[0];
#pragma unroll
        for (int j = 0; j < 64; j++) s += part[j];
        out[g] = s;
    }
}

// ---------------- launcher ----------------------------------------------------
extern "C" void kernel_launch(void* const* d_in, const int* in_sizes, int n_in,
                              void* d_out, int out_size) {
    const float* x     = (const float*)d_in[0];
    const int*   ei    = (const int*)d_in[1];
    const float* xs    = (const float*)d_in[2];
    const int*   batch = (const int*)d_in[3];
    const float* W0  = (const float*)d_in[4];
    const float* b0  = (const float*)d_in[5];
    const float* W1  = (const float*)d_in[6];
    const float* b1  = (const float*)d_in[7];
    const float* W2  = (const float*)d_in[8];
    const float* b2  = (const float*)d_in[9];
    const float* W3  = (const float*)d_in[10];
    const float* b3  = (const float*)d_in[11];
    const float* Wl1 = (const float*)d_in[12];
    const float* bl1 = (const float*)d_in[13];
    const float* Wl2 = (const float*)d_in[14];
    const float* bl2 = (const float*)d_in[15];
    float* out = (float*)d_out;

    const int* srcp = ei;
    const int* dstp = ei + EE;

    cudaFuncSetAttribute(k_gemm_mma, cudaFuncAttributeMaxDynamicSharedMemorySize, SMEM_MMA);

    uint32_t *gp, *hp;
    cudaGetSymbolAddress((void**)&gp, d_g);
    cudaGetSymbolAddress((void**)&hp, d_h);

    static cudaStream_t s1 = [] {
        cudaStream_t s;
        cudaStreamCreateWithFlags(&s, cudaStreamNonBlocking);
        return s;
    }();
    static cudaEvent_t ev_fork = [] {
        cudaEvent_t e; cudaEventCreateWithFlags(&e, cudaEventDisableTiming); return e;
    }();
    static cudaEvent_t ev_dinv = [] {
        cudaEvent_t e; cudaEventCreateWithFlags(&e, cudaEventDisableTiming); return e;
    }();
    static cudaEvent_t ev_join = [] {
        cudaEvent_t e; cudaEventCreateWithFlags(&e, cudaEventDisableTiming); return e;
    }();
    static cudaEvent_t ev_a = [] {
        cudaEvent_t e; cudaEventCreateWithFlags(&e, cudaEventDisableTiming); return e;
    }();
    static cudaEvent_t ev_m = [] {
        cudaEvent_t e; cudaEventCreateWithFlags(&e, cudaEventDisableTiming); return e;
    }();

    // fork: wconv (independent) runs on s1 alongside the CSR build
    cudaEventRecord(ev_fork, 0);
    cudaStreamWaitEvent(s1, ev_fork, 0);
    k_wconv_all<<<192, 256, 0, s1>>>(W1, W2, W3);

    // main stream: init + degree + CSR build
    k_init<<<500, 256>>>();
    k_count<<<(EE + 255) / 256, 256>>>(dstp);
    k_scan1<<<NB, 256>>>();
    cudaEventRecord(ev_dinv, 0);
    cudaStreamWaitEvent(s1, ev_dinv, 0);
    k_gemm0<<<1024, 256, 0, s1>>>(x, W0); // overlaps scan3+fill
    cudaEventRecord(ev_join, s1);

    k_scan3<<<NB, 256>>>();
    k_fill<<<(EE + 255) / 256, 256>>>(srcp, dstp);
    cudaStreamWaitEvent(0, ev_join, 0);   // d_g + d_whi ready

    // layers 1..3: chunked gather/GEMM software pipeline across two streams
    const float* biases[3] = {b0, b1, b2};
    uint32_t* bufs[4] = {gp, hp, gp, hp};
    for (int L = 0; L < 3; L++) {
        const uint32_t* in = bufs[L];
        uint32_t* o = bufs[L + 1];
        k_gatherA<<<CHUNK_N / 16, 256>>>(in, biases[L], 0);
        cudaEventRecord(ev_a, 0);
        cudaStreamWaitEvent(s1, ev_a, 0);
        k_gemm_mma<<<NSM, 512, SMEM_MMA, s1>>>(L, o, 0, CHUNK_T);   // ∥ gather chunk1
        cudaEventRecord(ev_m, s1);
        k_gatherA<<<(NN - CHUNK_N) / 16, 256>>>(in, biases[L], CHUNK_N);
        k_gemm_mma<<<NSM, 512, SMEM_MMA>>>(L, o, CHUNK_T, GT128);
        cudaStreamWaitEvent(0, ev_m, 0);  // both chunks of p ready
    }

    // fused gather + pool + head
    k_gpool<<<NN / 16, 256>>>(hp, batch, b3);
    k_mlp<<<GG, 64>>>(xs, Wl1, bl1, Wl2, bl2, out);
}

// round 17
// speedup vs baseline: 1.0259x; 1.0259x over previous
#include <cuda_runtime.h>
#include <cuda_bf16.h>
#include <cstdint>

#define NN 100000
#define EE 600000
#define GG 1000
#define GT128 782    // ceil(NN/128)
#define NB 391       // ceil(NN/256)
#define NSM 148

// ---------------- static device scratch --------------------------------------
__device__ float d_dinv[NN];
__device__ uint32_t d_g[(size_t)NN * 64];    // ping: p packed bf16x2 (128 bf16/row)
__device__ uint32_t d_h[(size_t)NN * 64];    // pong
__device__ uint32_t d_ahi[(size_t)NN * 64];  // A packed bf16
__device__ float d_pool[GG * 128];
__device__ float d_pcnt[GG];
__device__ int   d_cnti[NN];
__device__ int   d_off[NN + 1];
__device__ int   d_cur[NN];
__device__ int   d_csr[EE];
__device__ int   d_bsum[NB + 1];
__device__ __nv_bfloat16 d_whi[3 * 128 * 128];   // W^T bf16 high, [layer][n][k]
__device__ __nv_bfloat16 d_wlo[3 * 128 * 128];   // W^T bf16 low

// ---------------- helpers ------------------------------------------------------
__device__ __forceinline__ uint32_t smem_u32(const void* p) {
    uint32_t a;
    asm("{ .reg .u64 t; cvta.to.shared.u64 t, %1; cvt.u32.u64 %0, t; }" : "=r"(a) : "l"(p));
    return a;
}
#define LDM_X4(r, addr) \
    asm volatile("ldmatrix.sync.aligned.m8n8.x4.shared.b16 {%0,%1,%2,%3}, [%4];" \
        : "=r"((r)[0]), "=r"((r)[1]), "=r"((r)[2]), "=r"((r)[3]) : "r"(addr))

__device__ __forceinline__ void mma_bf16(float* c, const uint32_t* a, const uint32_t* b) {
    asm volatile("mma.sync.aligned.m16n8k16.row.col.f32.bf16.bf16.f32 "
        "{%0,%1,%2,%3}, {%4,%5,%6,%7}, {%8,%9}, {%0,%1,%2,%3};"
        : "+f"(c[0]), "+f"(c[1]), "+f"(c[2]), "+f"(c[3])
        : "r"(a[0]), "r"(a[1]), "r"(a[2]), "r"(a[3]), "r"(b[0]), "r"(b[1]));
}

__device__ __forceinline__ uint32_t pkbf(float a, float b) {
    __nv_bfloat162 t = __floats2bfloat162_rn(a, b);
    return *(uint32_t*)&t;
}
__device__ __forceinline__ void b2f8(uint4 u, float* f) {
    float2 f0 = __bfloat1622float2(*(__nv_bfloat162*)&u.x);
    float2 f1 = __bfloat1622float2(*(__nv_bfloat162*)&u.y);
    float2 f2 = __bfloat1622float2(*(__nv_bfloat162*)&u.z);
    float2 f3 = __bfloat1622float2(*(__nv_bfloat162*)&u.w);
    f[0] = f0.x; f[1] = f0.y; f[2] = f1.x; f[3] = f1.y;
    f[4] = f2.x; f[5] = f2.y; f[6] = f3.x; f[7] = f3.y;
}

// CSR gather, half-warp per node: lane l (0..15) owns cols 8l..8l+7 (one uint4).
__device__ __forceinline__ void gather_row_bf8(const uint4* __restrict__ P,
                                               int m, int l, float* out8) {
    float a[8], b[8];
    b2f8(__ldg(&P[(size_t)m * 16 + l]), a);
#pragma unroll
    for (int i = 0; i < 8; i++) b[i] = 0.f;
    int beg = __ldg(&d_off[m]), end = __ldg(&d_off[m + 1]);
    int e = beg;
    for (; e + 1 < end; e += 2) {
        int s0 = __ldg(&d_csr[e]);
        int s1 = __ldg(&d_csr[e + 1]);
        uint4 u0 = __ldg(&P[(size_t)s0 * 16 + l]);
        uint4 u1 = __ldg(&P[(size_t)s1 * 16 + l]);
        float x0[8], x1[8];
        b2f8(u0, x0);
        b2f8(u1, x1);
#pragma unroll
        for (int i = 0; i < 8; i++) { a[i] += x0[i]; b[i] += x1[i]; }
    }
    if (e < end) {
        int s0 = __ldg(&d_csr[e]);
        float x0[8];
        b2f8(__ldg(&P[(size_t)s0 * 16 + l]), x0);
#pragma unroll
        for (int i = 0; i < 8; i++) a[i] += x0[i];
    }
#pragma unroll
    for (int i = 0; i < 8; i++) out8[i] = a[i] + b[i];
}

// ---------------- init / degree / CSR ------------------------------------------
__global__ void k_init_cnt() {                 // critical path: cnt only
    int i = blockIdx.x * 256 + threadIdx.x;
    if (i < NN) d_cnti[i] = 0;
}
__global__ void k_init_pool() {                // side stream: pool + pcnt
    int i = blockIdx.x * 256 + threadIdx.x;
    if (i < GG * 128) d_pool[i] = 0.f;
    if (i < GG) d_pcnt[i] = 0.f;
}
__global__ void k_count(const int* __restrict__ dst) {
    int e = blockIdx.x * 256 + threadIdx.x;
    if (e < EE) atomicAdd(&d_cnti[dst[e]], 1);
}
__global__ void k_scan1() {
    __shared__ int s[256];
    int b = blockIdx.x, t = threadIdx.x;
    int i = b * 256 + t;
    int v = (i < NN) ? d_cnti[i] : 0;
    if (i < NN) d_dinv[i] = rsqrtf((float)(v + 1));
    s[t] = v;
    __syncthreads();
#pragma unroll
    for (int off = 1; off < 256; off <<= 1) {
        int x = (t >= off) ? s[t - off] : 0;
        __syncthreads();
        s[t] += x;
        __syncthreads();
    }
    if (i < NN) d_off[i] = s[t] - v;
    if (t == 255) d_bsum[b] = s[255];
}
__global__ void k_scan3() {
    __shared__ int sh[256];
    int b = blockIdx.x, t = threadIdx.x;
    int part = 0;
    for (int i = t; i < b; i += 256) part += d_bsum[i];
    sh[t] = part;
    __syncthreads();
#pragma unroll
    for (int off = 128; off > 0; off >>= 1) {
        if (t < off) sh[t] += sh[t + off];
        __syncthreads();
    }
    int base = sh[0];
    int i = b * 256 + t;
    if (i < NN) {
        int o = d_off[i] + base;
        d_off[i] = o;
        d_cur[i] = o;
    }
    if (i == 0) d_off[NN] = EE;
}
__global__ void k_fill(const int* __restrict__ src, const int* __restrict__ dst) {
    int e = blockIdx.x * 256 + threadIdx.x;
    if (e < EE) {
        int pos = atomicAdd(&d_cur[dst[e]], 1);
        d_csr[pos] = src[e];
    }
}

// ---------------- all W -> bf16 hi/lo, transposed [n][k] -----------------------
__global__ void k_wconv_all(const float* __restrict__ W1, const float* __restrict__ W2,
                            const float* __restrict__ W3) {
    int idx = blockIdx.x * 256 + threadIdx.x;
    int layer = idx >> 14;
    int r = idx & 16383;
    const float* W = (layer == 0) ? W1 : (layer == 1) ? W2 : W3;
    int n = r & 127, k = r >> 7;
    float wv = __ldg(&W[k * 128 + n]);
    __nv_bfloat16 hb = __float2bfloat16_rn(wv);
    __nv_bfloat16 lb = __float2bfloat16_rn(wv - __bfloat162float(hb));
    d_whi[layer * 16384 + n * 128 + k] = hb;
    d_wlo[layer * 16384 + n * 128 + k] = lb;
}

// ---------------- layer 0: p0 = bf16(dinv * (x @ W0)), K=4 --------------------
__global__ void k_gemm0(const float* __restrict__ x, const float* __restrict__ W0) {
    int t = threadIdx.x;
    int j = t & 31;
    float w[16];
#pragma unroll
    for (int k = 0; k < 4; k++)
#pragma unroll
        for (int c = 0; c < 4; c++)
            w[k * 4 + c] = __ldg(&W0[k * 128 + j * 4 + c]);
    int gw = blockIdx.x * 8 + (t >> 5);
    for (int n = gw; n < NN; n += gridDim.x * 8) {
        float4 xv = __ldg((const float4*)x + n);
        float di = d_dinv[n];
        float4 r;
        r.x = di * (xv.x * w[0] + xv.y * w[4] + xv.z * w[8]  + xv.w * w[12]);
        r.y = di * (xv.x * w[1] + xv.y * w[5] + xv.z * w[9]  + xv.w * w[13]);
        r.z = di * (xv.x * w[2] + xv.y * w[6] + xv.z * w[10] + xv.w * w[14]);
        r.w = di * (xv.x * w[3] + xv.y * w[7] + xv.z * w[11] + xv.w * w[15]);
        ((uint2*)d_g)[(size_t)n * 32 + j] = make_uint2(pkbf(r.x, r.y), pkbf(r.z, r.w));
    }
}

// ---- gather + transform: A[v] = bf16(relu(dinv*s + b)), half-warp/node --------
__global__ void k_gatherA(const uint32_t* __restrict__ in, const float* __restrict__ bias) {
    int v = blockIdx.x * 16 + (threadIdx.x >> 4);   // grid NN/16 = 6250 exact
    int l = threadIdx.x & 15;
    float s[8];
    gather_row_bf8((const uint4*)in, v, l, s);
    float di = __ldg(&d_dinv[v]);
    float4 b0 = __ldg((const float4*)bias + 2 * l);
    float4 b1 = __ldg((const float4*)bias + 2 * l + 1);
    float a0 = fmaxf(fmaf(di, s[0], b0.x), 0.f);
    float a1 = fmaxf(fmaf(di, s[1], b0.y), 0.f);
    float a2 = fmaxf(fmaf(di, s[2], b0.z), 0.f);
    float a3 = fmaxf(fmaf(di, s[3], b0.w), 0.f);
    float a4 = fmaxf(fmaf(di, s[4], b1.x), 0.f);
    float a5 = fmaxf(fmaf(di, s[5], b1.y), 0.f);
    float a6 = fmaxf(fmaf(di, s[6], b1.z), 0.f);
    float a7 = fmaxf(fmaf(di, s[7], b1.w), 0.f);
    uint4 o;
    o.x = pkbf(a0, a1); o.y = pkbf(a2, a3);
    o.z = pkbf(a4, a5); o.w = pkbf(a6, a7);
    ((uint4*)d_ahi)[(size_t)v * 16 + l] = o;
}

// ---------------- persistent HMMA GEMM: p = bf16(dinv * (A @ W)) --------------
#define PITCH 136
#define A_BUF0 0
#define A_BUF1 34816
#define B_HI 69632
#define B_LO 104448
#define SMEM_MMA 139264

__global__ void __launch_bounds__(512) k_gemm_mma(int layer, uint32_t* __restrict__ out) {
    extern __shared__ char smb[];
    uint32_t sbase = smem_u32(smb);
    int t = threadIdx.x, w = t >> 5, l = t & 31;

    const uint4* AH = (const uint4*)d_ahi;
    int tile0 = blockIdx.x;

    // ---- prologue: async-load A(tile0) into buf0 ----
    {
        int m128 = tile0 * 128;
#pragma unroll
        for (int i = t; i < 2048; i += 512) {
            int r = i >> 4, j = i & 15;
            int m = m128 + r;
            int mc = (m < NN) ? m : (NN - 1);
            int pb = (m < NN) ? 16 : 0;
            uint32_t dst = sbase + A_BUF0 + (uint32_t)((r * PITCH + j * 8) * 2);
            asm volatile("cp.async.cg.shared.global [%0], [%1], 16, %2;"
                         :: "r"(dst), "l"(&AH[(size_t)mc * 16 + j]), "r"(pb));
        }
        asm volatile("cp.async.commit_group;" ::: "memory");
    }

    // ---- W hi/lo into smem (once) ----
    const uint4* WH = (const uint4*)(d_whi + layer * 16384);
    const uint4* WL = (const uint4*)(d_wlo + layer * 16384);
#pragma unroll
    for (int i = t; i < 2048; i += 512) {
        int n = i >> 4, k8 = (i & 15) * 8;
        int off = (n * PITCH + k8) * 2;
        *(uint4*)(smb + B_HI + off) = __ldg(&WH[i]);
        *(uint4*)(smb + B_LO + off) = __ldg(&WL[i]);
    }
    asm volatile("cp.async.wait_group 0;" ::: "memory");
    __syncthreads();

    // ---- per-warp constant fragment addressing ----
    int rs = (w >> 1) * 16;
    int cb = (w & 1) * 64;
    int arow = rs + (l & 7) + ((l >> 3) & 1) * 8;
    int acol8 = (l >> 4) * 8;
    uint32_t a_frag = sbase + (uint32_t)((arow * PITCH + acol8) * 2);
    int brow = (l & 7) + (l >> 4) * 8;
    int bk8  = ((l >> 3) & 1) * 8;

    int par = 0;
    for (int tile = tile0; tile < GT128; tile += gridDim.x, par ^= 1) {
        // ---- prefetch next A tile into the other buffer ----
        int next = tile + gridDim.x;
        if (next < GT128) {
            int m128 = next * 128;
            uint32_t boff = (par == 0) ? A_BUF1 : A_BUF0;
#pragma unroll
            for (int i = t; i < 2048; i += 512) {
                int r = i >> 4, j = i & 15;
                int m = m128 + r;
                int mc = (m < NN) ? m : (NN - 1);
                int pb = (m < NN) ? 16 : 0;
                uint32_t dst = sbase + boff + (uint32_t)((r * PITCH + j * 8) * 2);
                asm volatile("cp.async.cg.shared.global [%0], [%1], 16, %2;"
                             :: "r"(dst), "l"(&AH[(size_t)mc * 16 + j]), "r"(pb));
            }
            asm volatile("cp.async.commit_group;" ::: "memory");
        }

        // ---- MMA on current buffer ----
        uint32_t a_base = a_frag + (par ? A_BUF1 : A_BUF0);
        float acc[32];
#pragma unroll
        for (int i = 0; i < 32; i++) acc[i] = 0.f;

#pragma unroll
        for (int kb = 0; kb < 8; kb++) {
            int k0 = kb * 16;
            uint32_t ah[4];
            LDM_X4(ah, a_base + k0 * 2);
#pragma unroll
            for (int np = 0; np < 4; np++) {
                int nb = cb + np * 16;
                uint32_t boff2 = (uint32_t)(((nb + brow) * PITCH + k0 + bk8) * 2);
                uint32_t bh[4], bl[4];
                LDM_X4(bh, sbase + B_HI + boff2);
                LDM_X4(bl, sbase + B_LO + boff2);
                float* c = acc + np * 8;
                mma_bf16(c,     ah, bh);
                mma_bf16(c,     ah, bl);
                mma_bf16(c + 4, ah, bh + 2);
                mma_bf16(c + 4, ah, bl + 2);
            }
        }

        // ---- epilogue: scale rows by dinv, store packed bf16 p ----
        int r0 = tile * 128 + rs + (l >> 2);
        int r1 = r0 + 8;
        float d0 = (r0 < NN) ? d_dinv[r0] : 0.f;
        float d1 = (r1 < NN) ? d_dinv[r1] : 0.f;
#pragma unroll
        for (int nt = 0; nt < 8; nt++) {
            int col = cb + nt * 8 + (l & 3) * 2;
            float* a = acc + nt * 4;
            if (r0 < NN) out[(size_t)r0 * 64 + (col >> 1)] = pkbf(a[0] * d0, a[1] * d0);
            if (r1 < NN) out[(size_t)r1 * 64 + (col >> 1)] = pkbf(a[2] * d1, a[3] * d1);
        }

        if (next < GT128)
            asm volatile("cp.async.wait_group 0;" ::: "memory");
        __syncthreads();
    }
}

// ---------------- fused gather + pooling (half-warp per node) ------------------
__global__ void k_gpool(const uint32_t* __restrict__ in, const int* __restrict__ batch,
                        const float* __restrict__ b3) {
    int v = blockIdx.x * 16 + (threadIdx.x >> 4);   // grid NN/16 exact
    int l = threadIdx.x & 15;
    float s[8];
    gather_row_bf8((const uint4*)in, v, l, s);
    float di = __ldg(&d_dinv[v]);
    float4 bb0 = __ldg((const float4*)b3 + 2 * l);
    float4 bb1 = __ldg((const float4*)b3 + 2 * l + 1);
    float o0 = fmaxf(fmaf(di, s[0], bb0.x), 0.f);
    float o1 = fmaxf(fmaf(di, s[1], bb0.y), 0.f);
    float o2 = fmaxf(fmaf(di, s[2], bb0.z), 0.f);
    float o3 = fmaxf(fmaf(di, s[3], bb0.w), 0.f);
    float o4 = fmaxf(fmaf(di, s[4], bb1.x), 0.f);
    float o5 = fmaxf(fmaf(di, s[5], bb1.y), 0.f);
    float o6 = fmaxf(fmaf(di, s[6], bb1.z), 0.f);
    float o7 = fmaxf(fmaf(di, s[7], bb1.w), 0.f);
    int g = __ldg(&batch[v]);
    float* p = d_pool + g * 128 + l * 8;
    asm volatile("red.global.add.v4.f32 [%0], {%1,%2,%3,%4};"
                 :: "l"(p), "f"(o0), "f"(o1), "f"(o2), "f"(o3) : "memory");
    asm volatile("red.global.add.v4.f32 [%0], {%1,%2,%3,%4};"
                 :: "l"(p + 4), "f"(o4), "f"(o5), "f"(o6), "f"(o7) : "memory");
    if (l == 0) atomicAdd(&d_pcnt[g], 1.0f);
}

// ---------------- final MLP ----------------------------------------------------
__global__ void k_mlp(const float* __restrict__ xs, const float* __restrict__ Wl1,
                      const float* __restrict__ bl1, const float* __restrict__ Wl2,
                      const float* __restrict__ bl2, float* __restrict__ out) {
    __shared__ float feat[132];
    __shared__ float part[64];
    int g = blockIdx.x, t = threadIdx.x;
    float inv = 1.0f / fmaxf(d_pcnt[g], 1.0f);
    for (int i = t; i < 132; i += 64)
        feat[i] = (i < 128) ? d_pool[g * 128 + i] * inv : xs[g * 4 + (i - 128)];
    __syncthreads();
    float h = bl1[t];
#pragma unroll 4
    for (int i = 0; i < 132; i++) h = fmaf(feat[i], Wl1[i * 64 + t], h);
    h = fmaxf(h, 0.f);
    part[t] = h * Wl2[t];
    __syncthreads();
    if (t == 0) {
        float s = bl2[0];
#pragma unroll
        for (int j = 0; j < 64; j++) s += part[j];
        out[g] = s;
    }
}

// ---------------- launcher ----------------------------------------------------
extern "C" void kernel_launch(void* const* d_in, const int* in_sizes, int n_in,
                              void* d_out, int out_size) {
    const float* x     = (const float*)d_in[0];
    const int*   ei    = (const int*)d_in[1];
    const float* xs    = (const float*)d_in[2];
    const int*   batch = (const int*)d_in[3];
    const float* W0  = (const float*)d_in[4];
    const float* b0  = (const float*)d_in[5];
    const float* W1  = (const float*)d_in[6];
    const float* b1  = (const float*)d_in[7];
    const float* W2  = (const float*)d_in[8];
    const float* b2  = (const float*)d_in[9];
    const float* W3  = (const float*)d_in[10];
    const float* b3  = (const float*)d_in[11];
    const float* Wl1 = (const float*)d_in[12];
    const float* bl1 = (const float*)d_in[13];
    const float* Wl2 = (const float*)d_in[14];
    const float* bl2 = (const float*)d_in[15];
    float* out = (float*)d_out;

    const int* srcp = ei;
    const int* dstp = ei + EE;

    cudaFuncSetAttribute(k_gemm_mma, cudaFuncAttributeMaxDynamicSharedMemorySize, SMEM_MMA);

    uint32_t *gp, *hp;
    cudaGetSymbolAddress((void**)&gp, d_g);
    cudaGetSymbolAddress((void**)&hp, d_h);

    static cudaStream_t s1 = [] {
        cudaStream_t s;
        cudaStreamCreateWithFlags(&s, cudaStreamNonBlocking);
        return s;
    }();
    static cudaEvent_t ev_fork = [] {
        cudaEvent_t e; cudaEventCreateWithFlags(&e, cudaEventDisableTiming); return e;
    }();
    static cudaEvent_t ev_dinv = [] {
        cudaEvent_t e; cudaEventCreateWithFlags(&e, cudaEventDisableTiming); return e;
    }();
    static cudaEvent_t ev_join = [] {
        cudaEvent_t e; cudaEventCreateWithFlags(&e, cudaEventDisableTiming); return e;
    }();

    // fork: pool-zero + wconv (independent) run on s1 alongside the CSR build
    cudaEventRecord(ev_fork, 0);
    cudaStreamWaitEvent(s1, ev_fork, 0);
    k_init_pool<<<(GG * 128 + 255) / 256, 256, 0, s1>>>();
    k_wconv_all<<<192, 256, 0, s1>>>(W1, W2, W3);

    // main stream: cnt init + degree + CSR build
    k_init_cnt<<<NB, 256>>>();
    k_count<<<(EE + 255) / 256, 256>>>(dstp);
    k_scan1<<<NB, 256>>>();
    cudaEventRecord(ev_dinv, 0);          // dinv ready
    cudaStreamWaitEvent(s1, ev_dinv, 0);
    k_gemm0<<<1024, 256, 0, s1>>>(x, W0); // overlaps scan3+fill
    cudaEventRecord(ev_join, s1);

    k_scan3<<<NB, 256>>>();
    k_fill<<<(EE + 255) / 256, 256>>>(srcp, dstp);
    cudaStreamWaitEvent(0, ev_join, 0);   // join: d_g + d_whi + pool-zero ready

    // layers 1..3: gather+transform -> bf16 A, pipelined persistent GEMM
    k_gatherA<<<NN / 16, 256>>>(gp, b0);
    k_gemm_mma<<<NSM, 512, SMEM_MMA>>>(0, hp);

    k_gatherA<<<NN / 16, 256>>>(hp, b1);
    k_gemm_mma<<<NSM, 512, SMEM_MMA>>>(1, gp);

    k_gatherA<<<NN / 16, 256>>>(gp, b2);
    k_gemm_mma<<<NSM, 512, SMEM_MMA>>>(2, hp);

    // fused gather + pool + head (half-warp per node)
    k_gpool<<<NN / 16, 256>>>(hp, batch, b3);
    k_mlp<<<GG, 64>>>(xs, Wl1, bl1, Wl2, bl2, out);
}